// round 13
// baseline (speedup 1.0000x reference)
#include <cuda_runtime.h>
#include <cstdint>

// Problem constants: B=64, S=512, A=8, D=128, C=1024
#define PB  64
#define PS  512
#define PA  8
#define PD  128

#define LEN_BLOCKS 64   // first LEN_BLOCKS blocks compute candidate_len
#define ITER 8          // candidates per warp
#define CPB 64          // candidates per gather block (8 warps * 8)
#define STAGES 4        // cp.async pipeline depth (LSU warps)
#define ROW_BYTES (PD * 4)   // 512

// ---- cp.async (LDGSTS) helpers ----
__device__ __forceinline__ unsigned smem_addr(const void* p) {
    return (unsigned)__cvta_generic_to_shared(p);
}
__device__ __forceinline__ void cpasync16(uint32_t dst_smem, const void* src) {
    asm volatile("cp.async.cg.shared.global [%0], [%1], 16;"
                 :: "r"(dst_smem), "l"(src));
}
__device__ __forceinline__ void cpcommit() {
    asm volatile("cp.async.commit_group;");
}
__device__ __forceinline__ void cpwait3() {
    asm volatile("cp.async.wait_group 3;");
}
__device__ __forceinline__ void cpwait0() {
    asm volatile("cp.async.wait_group 0;");
}

// ---- bulk-copy / mbarrier helpers ----
__device__ __forceinline__ void mbar_init(void* mbar, unsigned count) {
    asm volatile("mbarrier.init.shared.b64 [%0], %1;"
                 :: "r"(smem_addr(mbar)), "r"(count) : "memory");
}
__device__ __forceinline__ void mbar_expect_tx(void* mbar, unsigned bytes) {
    asm volatile("mbarrier.arrive.expect_tx.shared.b64 _, [%0], %1;"
                 :: "r"(smem_addr(mbar)), "r"(bytes) : "memory");
}
__device__ __forceinline__ void mbar_wait(void* mbar, unsigned parity) {
    asm volatile(
        "{\n\t.reg .pred P1;\n\t"
        "WAIT_LOOP_%=:\n\t"
        "mbarrier.try_wait.parity.acquire.cta.shared::cta.b64 P1, [%0], %1, 0x989680;\n\t"
        "@P1 bra.uni WAIT_DONE_%=;\n\t"
        "bra.uni WAIT_LOOP_%=;\n\t"
        "WAIT_DONE_%=:\n\t}"
        :: "r"(smem_addr(mbar)), "r"(parity) : "memory");
}
__device__ __forceinline__ void bulk_g2s(void* sdst, const void* gsrc,
                                         unsigned bytes, void* mbar) {
    asm volatile(
        "cp.async.bulk.shared::cluster.global.mbarrier::complete_tx::bytes "
        "[%0], [%1], %2, [%3];"
        :: "r"(smem_addr(sdst)), "l"(gsrc), "r"(bytes), "r"(smem_addr(mbar))
        : "memory");
}
__device__ __forceinline__ void bulk_s2g(void* gdst, const void* ssrc,
                                         unsigned bytes) {
    asm volatile(
        "cp.async.bulk.global.shared::cta.bulk_group [%0], [%1], %2;"
        :: "l"(gdst), "r"(smem_addr(ssrc)), "r"(bytes) : "memory");
}
__device__ __forceinline__ void bulk_commit() {
    asm volatile("cp.async.bulk.commit_group;" ::: "memory");
}
__device__ __forceinline__ void bulk_wait0() {
    asm volatile("cp.async.bulk.wait_group 0;" ::: "memory");
}
__device__ __forceinline__ void fence_proxy_async_cta() {
    asm volatile("fence.proxy.async.shared::cta;" ::: "memory");
}

// ---------------------------------------------------------------------------
// blocks [0,64):  candidate_len per batch (independent role, reads inputs).
// blocks [64,..): gather, HYBRID dual-engine:
//   warps 0-3: cp.async (LDGSTS) depth-4 pipeline -> LDS -> mask -> STG.128
//   warps 4-7: bulk TMA G2S (per-warp mbarrier) -> S2G (zero row if mask==0)
//   The two halves use disjoint issue paths (LSU vs copy engine) in parallel.
// ---------------------------------------------------------------------------
__global__ void __launch_bounds__(256)
cand_kernel(const float*  __restrict__ word_repr,
            const int*    __restrict__ anchor_cls,
            const int*    __restrict__ anchor_loc,
            const int*    __restrict__ cand_idx,
            float*        __restrict__ out,
            long long off_label,
            long long off_mask,
            long long off_loc,
            long long off_len,
            long long off_scalar,   // -1 if absent
            float scalar_val,
            int BC, int C)
{
    if (blockIdx.x < LEN_BLOCKS) {
        // ---- len role ----
        __shared__ int rsm[8];
        int batch = blockIdx.x;
        int base  = batch * C;

        int sum = 0;
        for (int i = threadIdx.x; i < C; i += blockDim.x) {
            int c = base + i;
            int b = cand_idx[3 * c + 0];
            int w = cand_idx[3 * c + 1];
            int a = cand_idx[3 * c + 2];
            long long flat = (((long long)b * PS + w) * PA + a);
            int2 loc = *reinterpret_cast<const int2*>(anchor_loc + flat * 2);
            sum += (loc.x != loc.y) ? 1 : 0;
        }
        #pragma unroll
        for (int o = 16; o > 0; o >>= 1)
            sum += __shfl_down_sync(0xFFFFFFFFu, sum, o);

        int lane = threadIdx.x & 31;
        int wid  = threadIdx.x >> 5;
        if (lane == 0) rsm[wid] = sum;
        __syncthreads();
        if (threadIdx.x == 0) {
            int total = 0;
            #pragma unroll
            for (int i = 0; i < 8; i++) total += rsm[i];
            __stcs(out + off_len + batch, fmaxf((float)total, 1.0f));
            if (batch == 0 && off_scalar >= 0)
                __stcs(out + off_scalar, scalar_val);
        }
        return;
    }

    // ---- gather role ----
    __shared__ __align__(16)  float s_stage[4][STAGES][PD];   // 8 KB (LSU warps)
    __shared__ __align__(128) float s_rows[32][PD];           // 16 KB (TMA warps)
    __shared__ __align__(128) float s_zero[PD];               // zero row
    __shared__ __align__(8) unsigned long long s_mbar[4];     // TMA warps
    __shared__ float s_label[CPB], s_maskv[CPB], s_locx[CPB], s_locy[CPB];

    int tid  = threadIdx.x;
    int wid  = tid >> 5;
    int lane = tid & 31;
    int cb   = (blockIdx.x - LEN_BLOCKS) * CPB;
    int c0   = cb + wid * ITER;       // this warp's first candidate

    // --- metadata: one coalesced 96B idx load per warp + shuffles ---
    int val = 0;
    if (lane < 3 * ITER) val = cand_idx[3 * c0 + lane];
    int bb = __shfl_sync(0xFFFFFFFFu, val, (lane < 8) ? 3 * lane + 0 : 0);
    int ww = __shfl_sync(0xFFFFFFFFu, val, (lane < 8) ? 3 * lane + 1 : 0);
    int aa = __shfl_sync(0xFFFFFFFFu, val, (lane < 8) ? 3 * lane + 2 : 0);
    long long myflat = (((long long)bb * PS + ww) * PA + aa);
    int flat_lo = (int)(myflat & 0xFFFFFFFFll);
    int flat_hi = (int)(myflat >> 32);

    float mymask = 0.0f;
    int   mym    = 0;
    if (lane < ITER) {
        int2 loc = *reinterpret_cast<const int2*>(anchor_loc + myflat * 2);
        int  cls = anchor_cls[myflat];
        mym = (loc.x != loc.y) ? 1 : 0;
        mymask = (float)mym;
        int l = wid * ITER + lane;
        s_label[l] = (float)cls;
        s_maskv[l] = mymask;
        s_locx[l]  = (float)loc.x;
        s_locy[l]  = (float)loc.y;
    }
    unsigned mbits = __ballot_sync(0xFFFFFFFFu, mym) & 0xFFu;

    // zero row + per-TMA-warp mbarrier init
    if (tid < PD) s_zero[tid] = 0.0f;
    if (wid >= 4 && lane == 0) mbar_init(&s_mbar[wid - 4], 1);
    fence_proxy_async_cta();
    __syncthreads();   // zero row + mbars visible before any async use

    if (wid < 4) {
        // ================= LSU path (cp.async pipeline) =================
        uint32_t stage_base = smem_addr(&s_stage[wid][0][0]);

        #pragma unroll
        for (int i = 0; i < STAGES; i++) {
            int lo = __shfl_sync(0xFFFFFFFFu, flat_lo, i);
            int hi = __shfl_sync(0xFFFFFFFFu, flat_hi, i);
            long long fl = ((long long)hi << 32) | (unsigned int)lo;
            cpasync16(stage_base + (uint32_t)(i * PD * 4) + lane * 16,
                      word_repr + fl * PD + lane * 4);
            cpcommit();
        }

        #pragma unroll
        for (int i = 0; i < ITER; i++) {
            cpwait3();
            int slot = i & (STAGES - 1);

            float mask = __shfl_sync(0xFFFFFFFFu, mymask, i);
            float4 t = *reinterpret_cast<float4*>(&s_stage[wid][slot][lane * 4]);
            t.x *= mask; t.y *= mask; t.z *= mask; t.w *= mask;
            __stcs(reinterpret_cast<float4*>(out + (long long)(c0 + i) * PD) + lane, t);

            if (i + STAGES < ITER) {
                int lo = __shfl_sync(0xFFFFFFFFu, flat_lo, i + STAGES);
                int hi = __shfl_sync(0xFFFFFFFFu, flat_hi, i + STAGES);
                long long fl = ((long long)hi << 32) | (unsigned int)lo;
                cpasync16(stage_base + (uint32_t)(slot * PD * 4) + lane * 16,
                          word_repr + fl * PD + lane * 4);
            }
            cpcommit();
        }
        cpwait0();
    } else {
        // ================= TMA path (bulk copies) =================
        int tw = wid - 4;
        if (lane == 0)
            mbar_expect_tx(&s_mbar[tw], __popc(mbits) * ROW_BYTES);
        #pragma unroll
        for (int i = 0; i < ITER; i++) {
            int lo = __shfl_sync(0xFFFFFFFFu, flat_lo, i);
            int hi = __shfl_sync(0xFFFFFFFFu, flat_hi, i);
            if (lane == 0 && ((mbits >> i) & 1)) {
                long long fl = ((long long)hi << 32) | (unsigned int)lo;
                bulk_g2s(&s_rows[tw * ITER + i][0], word_repr + fl * PD,
                         ROW_BYTES, &s_mbar[tw]);
            }
        }

        mbar_wait(&s_mbar[tw], 0);
        if (lane < ITER) {
            const float* src = mym ? &s_rows[tw * ITER + lane][0] : &s_zero[0];
            bulk_s2g(out + (long long)(c0 + lane) * PD, src, ROW_BYTES);
            bulk_commit();
            bulk_wait0();
        }
    }

    __syncthreads();

    // Coalesced flush of the staged small outputs.
    if (tid < CPB) {
        __stcs(out + off_label + cb + tid, s_label[tid]);
        __stcs(out + off_mask  + cb + tid, s_maskv[tid]);
    }
    if (tid < 2 * CPB) {
        float v = (tid & 1) ? s_locy[tid >> 1] : s_locx[tid >> 1];
        __stcs(out + off_loc + 2 * (long long)cb + tid, v);
    }
}

// ---------------------------------------------------------------------------
// Host launcher
// ---------------------------------------------------------------------------
extern "C" void kernel_launch(void* const* d_in, const int* in_sizes, int n_in,
                              void* d_out, int out_size)
{
    const float* word_repr  = (const float*)d_in[0];  // (B,S,A,D) fp32
    const int*   anchor_cls = (const int*)d_in[1];    // (B,S,A)   int32
    const int*   anchor_loc = (const int*)d_in[2];    // (B,S,A,2) int32
    const int*   cand_idx   = (const int*)d_in[3];    // (B*C, 3)  int32
    float* out = (float*)d_out;

    int BC = in_sizes[3] / 3;          // 65536
    int C  = BC / PB;                  // 1024

    // Output tuple layout (reference return order):
    //   repr (B*C*D) | label (B*C) | [num (1)] | len (B) | mask (B*C) | loc (B*C*2)
    long long n_repr = (long long)BC * PD;
    long long total_with_scalar = n_repr + BC + 1 + PB + BC + 2LL * BC;

    long long off_label = n_repr;
    long long off_scalar, off_len;
    if ((long long)out_size >= total_with_scalar) {
        off_scalar = off_label + BC;
        off_len    = off_scalar + 1;
    } else {
        off_scalar = -1;
        off_len    = off_label + BC;
    }
    long long off_mask = off_len + PB;
    long long off_loc  = off_mask + BC;

    int threads = 256;
    int blocks  = LEN_BLOCKS + (BC + CPB - 1) / CPB;   // 64 + 1024
    cand_kernel<<<blocks, threads>>>(word_repr, anchor_cls, anchor_loc,
                                     cand_idx, out,
                                     off_label, off_mask, off_loc,
                                     off_len, off_scalar,
                                     (float)C, BC, C);
}

// round 14
// speedup vs baseline: 1.0200x; 1.0200x over previous
#include <cuda_runtime.h>
#include <cstdint>

// Problem constants: B=64, S=512, A=8, D=128, C=1024
#define PB  64
#define PS  512
#define PA  8
#define PD  128

#define LEN_BLOCKS 64   // first LEN_BLOCKS blocks compute candidate_len
#define ITER 8          // candidates per warp
#define CPB  64         // candidates per block = 8 warps * ITER
#define STAGES 4        // cp.async pipeline depth

__device__ __forceinline__ void cpasync16(uint32_t dst_smem, const void* src) {
    asm volatile("cp.async.cg.shared.global [%0], [%1], 16;"
                 :: "r"(dst_smem), "l"(src));
}
__device__ __forceinline__ void cpcommit() {
    asm volatile("cp.async.commit_group;");
}
__device__ __forceinline__ void cpwait3() {
    asm volatile("cp.async.wait_group 3;");
}
__device__ __forceinline__ void cpwait0() {
    asm volatile("cp.async.wait_group 0;");
}

// ---------------------------------------------------------------------------
// blocks [0,64):  candidate_len per batch. MLP-optimized: each thread owns 4
//   consecutive candidates -> 3 aligned int4 idx loads (independent), then 4
//   independent loc loads. Dependency depth 2, MLP 3-4 (was: serial depth-8).
// blocks [64,..): gather — R10 structure unchanged (cp.async depth-4 pipeline,
//   SMEM-staged small outputs, coalesced flush).
// ---------------------------------------------------------------------------
__global__ void __launch_bounds__(256)
cand_kernel(const float*  __restrict__ word_repr,
            const int*    __restrict__ anchor_cls,
            const int*    __restrict__ anchor_loc,
            const int*    __restrict__ cand_idx,
            float*        __restrict__ out,
            long long off_label,
            long long off_mask,
            long long off_loc,
            long long off_len,
            long long off_scalar,   // -1 if absent
            float scalar_val,
            int BC, int C)
{
    if (blockIdx.x < LEN_BLOCKS) {
        // ---- len role (MLP-unrolled) ----
        __shared__ int rsm[8];
        int batch = blockIdx.x;
        int c4 = batch * C + threadIdx.x * 4;     // 4 consecutive candidates

        // 48B of idx data = 3 aligned int4 loads, all independent.
        const int4* ip = reinterpret_cast<const int4*>(cand_idx + 3 * c4);
        int4 q0 = ip[0];
        int4 q1 = ip[1];
        int4 q2 = ip[2];

        // triples: (q0.x q0.y q0.z) (q0.w q1.x q1.y) (q1.z q1.w q2.x) (q2.y q2.z q2.w)
        long long f0 = (((long long)q0.x * PS + q0.y) * PA + q0.z);
        long long f1 = (((long long)q0.w * PS + q1.x) * PA + q1.y);
        long long f2 = (((long long)q1.z * PS + q1.w) * PA + q2.x);
        long long f3 = (((long long)q2.y * PS + q2.z) * PA + q2.w);

        // 4 independent loc loads (MLP=4).
        int2 l0 = *reinterpret_cast<const int2*>(anchor_loc + f0 * 2);
        int2 l1 = *reinterpret_cast<const int2*>(anchor_loc + f1 * 2);
        int2 l2 = *reinterpret_cast<const int2*>(anchor_loc + f2 * 2);
        int2 l3 = *reinterpret_cast<const int2*>(anchor_loc + f3 * 2);

        int sum = (l0.x != l0.y) + (l1.x != l1.y) + (l2.x != l2.y) + (l3.x != l3.y);

        #pragma unroll
        for (int o = 16; o > 0; o >>= 1)
            sum += __shfl_down_sync(0xFFFFFFFFu, sum, o);

        int lane = threadIdx.x & 31;
        int wid  = threadIdx.x >> 5;
        if (lane == 0) rsm[wid] = sum;
        __syncthreads();
        if (threadIdx.x == 0) {
            int total = 0;
            #pragma unroll
            for (int i = 0; i < 8; i++) total += rsm[i];
            __stcs(out + off_len + batch, fmaxf((float)total, 1.0f));
            if (batch == 0 && off_scalar >= 0)
                __stcs(out + off_scalar, scalar_val);
        }
        return;
    }

    // ---- gather role (R10) ----
    __shared__ __align__(16) float s_stage[8][STAGES][PD]; // 16 KB
    __shared__ float s_label[CPB];
    __shared__ float s_mask [CPB];
    __shared__ float s_locx [CPB];
    __shared__ float s_locy [CPB];

    int wid  = threadIdx.x >> 5;
    int lane = threadIdx.x & 31;
    int cb   = (blockIdx.x - LEN_BLOCKS) * CPB;
    int c0   = cb + wid * ITER;

    // --- prologue: all 8 flats via one coalesced idx load + shuffles ---
    int val = 0;
    if (lane < 3 * ITER) val = cand_idx[3 * c0 + lane];

    int bb = __shfl_sync(0xFFFFFFFFu, val, (lane < 8) ? 3 * lane + 0 : 0);
    int ww = __shfl_sync(0xFFFFFFFFu, val, (lane < 8) ? 3 * lane + 1 : 0);
    int aa = __shfl_sync(0xFFFFFFFFu, val, (lane < 8) ? 3 * lane + 2 : 0);
    long long myflat = (((long long)bb * PS + ww) * PA + aa);
    int flat_lo = (int)(myflat & 0xFFFFFFFFll);
    int flat_hi = (int)(myflat >> 32);

    uint32_t stage_base = (uint32_t)__cvta_generic_to_shared(&s_stage[wid][0][0]);

    #pragma unroll
    for (int i = 0; i < STAGES; i++) {
        int lo = __shfl_sync(0xFFFFFFFFu, flat_lo, i);
        int hi = __shfl_sync(0xFFFFFFFFu, flat_hi, i);
        long long fl = ((long long)hi << 32) | (unsigned int)lo;
        const float* src = word_repr + fl * PD + lane * 4;
        cpasync16(stage_base + (uint32_t)(i * PD * 4) + lane * 16, src);
        cpcommit();
    }

    // loc/cls for my candidate (lanes 0..7), overlapping the cp.asyncs.
    float mymask = 0.0f;
    if (lane < ITER) {
        int2 loc = *reinterpret_cast<const int2*>(anchor_loc + myflat * 2);
        int  cls = anchor_cls[myflat];
        mymask = (loc.x != loc.y) ? 1.0f : 0.0f;
        int l = wid * ITER + lane;
        s_label[l] = (float)cls;
        s_mask [l] = mymask;
        s_locx [l] = (float)loc.x;
        s_locy [l] = (float)loc.y;
    }

    // --- main pipeline ---
    #pragma unroll
    for (int i = 0; i < ITER; i++) {
        cpwait3();
        int slot = i & (STAGES - 1);

        float mask = __shfl_sync(0xFFFFFFFFu, mymask, i);
        float4 t = *reinterpret_cast<float4*>(&s_stage[wid][slot][lane * 4]);
        t.x *= mask; t.y *= mask; t.z *= mask; t.w *= mask;
        __stcs(reinterpret_cast<float4*>(out + (long long)(c0 + i) * PD) + lane, t);

        if (i + STAGES < ITER) {
            int lo = __shfl_sync(0xFFFFFFFFu, flat_lo, i + STAGES);
            int hi = __shfl_sync(0xFFFFFFFFu, flat_hi, i + STAGES);
            long long fl = ((long long)hi << 32) | (unsigned int)lo;
            const float* src = word_repr + fl * PD + lane * 4;
            cpasync16(stage_base + (uint32_t)(slot * PD * 4) + lane * 16, src);
        }
        cpcommit();
    }
    cpwait0();

    __syncthreads();

    // Coalesced flush of the staged small outputs.
    int t = threadIdx.x;
    if (t < CPB) {
        __stcs(out + off_label + cb + t, s_label[t]);
        __stcs(out + off_mask  + cb + t, s_mask[t]);
    }
    if (t < 2 * CPB) {
        float v = (t & 1) ? s_locy[t >> 1] : s_locx[t >> 1];
        __stcs(out + off_loc + 2 * (long long)cb + t, v);
    }
}

// ---------------------------------------------------------------------------
// Host launcher
// ---------------------------------------------------------------------------
extern "C" void kernel_launch(void* const* d_in, const int* in_sizes, int n_in,
                              void* d_out, int out_size)
{
    const float* word_repr  = (const float*)d_in[0];  // (B,S,A,D) fp32
    const int*   anchor_cls = (const int*)d_in[1];    // (B,S,A)   int32
    const int*   anchor_loc = (const int*)d_in[2];    // (B,S,A,2) int32
    const int*   cand_idx   = (const int*)d_in[3];    // (B*C, 3)  int32
    float* out = (float*)d_out;

    int BC = in_sizes[3] / 3;          // 65536
    int C  = BC / PB;                  // 1024

    // Output tuple layout (reference return order):
    //   repr (B*C*D) | label (B*C) | [num (1)] | len (B) | mask (B*C) | loc (B*C*2)
    long long n_repr = (long long)BC * PD;
    long long total_with_scalar = n_repr + BC + 1 + PB + BC + 2LL * BC;

    long long off_label = n_repr;
    long long off_scalar, off_len;
    if ((long long)out_size >= total_with_scalar) {
        off_scalar = off_label + BC;
        off_len    = off_scalar + 1;
    } else {
        off_scalar = -1;
        off_len    = off_label + BC;
    }
    long long off_mask = off_len + PB;
    long long off_loc  = off_mask + BC;

    int threads = 256;                                        // 8 warps/block
    int blocks  = LEN_BLOCKS + (BC + CPB - 1) / CPB;          // 64 + 1024
    cand_kernel<<<blocks, threads>>>(word_repr, anchor_cls, anchor_loc,
                                     cand_idx, out,
                                     off_label, off_mask, off_loc,
                                     off_len, off_scalar,
                                     (float)C, BC, C);
}